// round 17
// baseline (speedup 1.0000x reference)
#include <cuda_runtime.h>
#include <cuda_bf16.h>
#include <cuda_fp16.h>

#define B_DIM 4
#define S_DIM 4096
#define F_DIM 512
#define D_DIM 64
#define EGRID 608
#define TOTAL_JOBS 16384   // 256 i-blocks(64) x 64 j-tiles(64)

// ---------------- scratch (no cudaMalloc allowed) ----------------
__device__ __half g_Qh[B_DIM * S_DIM * D_DIM];
__device__ __half g_Kh[B_DIM * S_DIM * D_DIM];
__device__ unsigned char g_Whs[8 * 16384];   // pre-swizzled W fp16 tiles
__device__ float2 g_rcp[8192];               // (1/max(|k-4096|,1), 1/max(|k-4097|,1))

typedef unsigned long long u64;
typedef unsigned u32;

__device__ __forceinline__ float fast_rcp(float x) {
    float r; asm("rcp.approx.f32 %0, %1;" : "=f"(r) : "f"(x)); return r;
}
__device__ __forceinline__ u32 smem_u32(const void* p) {
    u32 a;
    asm("{ .reg .u64 t; cvta.to.shared.u64 t, %1; cvt.u32.u64 %0, t; }" : "=r"(a) : "l"(p));
    return a;
}
__device__ __forceinline__ void ldsm_x4(u32& r0, u32& r1, u32& r2, u32& r3, u32 addr) {
    asm volatile("ldmatrix.sync.aligned.m8n8.x4.shared.b16 {%0,%1,%2,%3}, [%4];"
                 : "=r"(r0), "=r"(r1), "=r"(r2), "=r"(r3) : "r"(addr));
}
// fp16 MMA, fp32 accumulate
__device__ __forceinline__ void mma16816h(float* c, const u32* a, const u32* b) {
    asm volatile(
        "mma.sync.aligned.m16n8k16.row.col.f32.f16.f16.f32 "
        "{%0,%1,%2,%3}, {%4,%5,%6,%7}, {%8,%9}, {%0,%1,%2,%3};"
        : "+f"(c[0]), "+f"(c[1]), "+f"(c[2]), "+f"(c[3])
        : "r"(a[0]), "r"(a[1]), "r"(a[2]), "r"(a[3]), "r"(b[0]), "r"(b[1]));
}
__device__ __forceinline__ void cp16(u32 dst, const void* src) {
    asm volatile("cp.async.cg.shared.global [%0], [%1], 16;" :: "r"(dst), "l"(src));
}
__device__ __forceinline__ void cp_commit() { asm volatile("cp.async.commit_group;" ::: "memory"); }
__device__ __forceinline__ void cp_wait0()  { asm volatile("cp.async.wait_group 0;" ::: "memory"); }
__device__ __forceinline__ void cp_wait1()  { asm volatile("cp.async.wait_group 1;" ::: "memory"); }

// =================================================================
// W setup: Wq|Wk -> single fp16 pre-swizzled tile images + rcp table
// =================================================================
__global__ __launch_bounds__(256) void wsetup_kernel(
    const float* __restrict__ Wq, const float* __restrict__ Wk)
{
    int idx = blockIdx.x * 256 + threadIdx.x;   // 8192 items
    {
        float d0 = fmaxf(fabsf((float)(idx - 4096)), 1.f);
        float d1 = fmaxf(fabsf((float)(idx - 4097)), 1.f);
        float2 r;
        r.x = fast_rcp(d0);
        r.y = fast_rcp(d1);
        g_rcp[idx] = r;
    }
    int c = idx >> 10;
    int j = (idx >> 3) & 127;
    int a = idx & 7;
    const float* wp = (j < 64) ? (Wq + j) : (Wk + (j - 64));
    int f0 = c * 64 + a * 8;
    float wv[8];
    #pragma unroll
    for (int k = 0; k < 8; ++k) wv[k] = wp[(size_t)(f0 + k) * D_DIM];
    uint4 H;
    __half2 h;
    h = __floats2half2_rn(wv[0], wv[1]); H.x = *(u32*)&h;
    h = __floats2half2_rn(wv[2], wv[3]); H.y = *(u32*)&h;
    h = __floats2half2_rn(wv[4], wv[5]); H.z = *(u32*)&h;
    h = __floats2half2_rn(wv[6], wv[7]); H.w = *(u32*)&h;
    u32 off = (u32)j * 128 + (u32)a * 16;
    u32 swo = off ^ ((off >> 3) & 0x70);
    *(uint4*)(g_Whs + c * 16384 + swo) = H;
}

// =================================================================
// proj: 64-row tiles, grid 256, 3 CTAs/SM. fp16 single-pass HMMA
// [64] x [128 = Q|K]; 1 barrier/chunk; F double-buffered; W prefetch
// issued AFTER the barrier (race-free); wch read direct from global.
// smem: F 0(2x8K), Wbuf 16K(2x16K), chRow 49152
// =================================================================
#define P_F   0
#define P_W   16384
#define P_CHR 49152
#define P_SMEM 49664

__global__ __launch_bounds__(256, 3) void proj_kernel(
    const float* __restrict__ feat, const float* __restrict__ wch,
    const float* __restrict__ bch, const float* __restrict__ loc_p)
{
    extern __shared__ char smem[];
    const u32 sb = smem_u32(smem);
    float* chRow = (float*)(smem + P_CHR);

    const int t = threadIdx.x;
    const int wid = t >> 5, lid = t & 31;
    const int wm = wid & 1, wn = wid >> 1;
    const int rowBase = blockIdx.x * 64;

    const int fr = t >> 2, ffo = (t & 3) * 16;
    const int watom = t * 16;

    const u32 lxor  = ((u32)(lid & 7)) << 4;
    const u32 abase = (u32)((wm * 32) + (lid & 7) + ((lid >> 3) & 1) * 8) * 128;
    const u32 ach   = ((u32)(lid >> 4) & 1) * 16;
    const u32 bbase4 = (u32)((wn * 32) + ((lid >> 4) & 1) * 8 + (lid & 7)) * 128;
    const u32 bk4    = ((u32)(lid >> 3) & 1) * 16;

    float acc[2][4][4] = {};
    float cs0 = 0.f, cs1 = 0.f, cs2 = 0.f, cs3 = 0.f;

    // prefetch W chunk 0 into buf 0
    {
        u32 wb = sb + P_W;
        #pragma unroll
        for (int a = 0; a < 4; ++a)
            cp16(wb + watom + a * 4096, g_Whs + watom + a * 4096);
        cp_commit();
    }

    // preload feat chunk 0 into registers
    const float* fbase = feat + (size_t)(rowBase + fr) * F_DIM + ffo;
    const float* wcb = wch + ffo;
    float4 v0 = *(const float4*)(fbase + 0);
    float4 v1 = *(const float4*)(fbase + 4);
    float4 v2 = *(const float4*)(fbase + 8);
    float4 v3 = *(const float4*)(fbase + 12);

    for (int c = 0; c < 8; ++c) {
        const u32 wb = sb + P_W + (c & 1) * 16384;
        const u32 fbo = P_F + (c & 1) * 8192;
        // ---- convert current chunk regs -> F buf + charge partials ----
        {
            const float* wc = wcb + c * 64;
            cs0 += v0.x * wc[0]  + v0.y * wc[1]  + v0.z * wc[2]  + v0.w * wc[3];
            cs1 += v1.x * wc[4]  + v1.y * wc[5]  + v1.z * wc[6]  + v1.w * wc[7];
            cs2 += v2.x * wc[8]  + v2.y * wc[9]  + v2.z * wc[10] + v2.w * wc[11];
            cs3 += v3.x * wc[12] + v3.y * wc[13] + v3.z * wc[14] + v3.w * wc[15];
            uint4 H0, H1;
            __half2 h;
            h = __floats2half2_rn(v0.x, v0.y); H0.x = *(u32*)&h;
            h = __floats2half2_rn(v0.z, v0.w); H0.y = *(u32*)&h;
            h = __floats2half2_rn(v1.x, v1.y); H0.z = *(u32*)&h;
            h = __floats2half2_rn(v1.z, v1.w); H0.w = *(u32*)&h;
            h = __floats2half2_rn(v2.x, v2.y); H1.x = *(u32*)&h;
            h = __floats2half2_rn(v2.z, v2.w); H1.y = *(u32*)&h;
            h = __floats2half2_rn(v3.x, v3.y); H1.z = *(u32*)&h;
            h = __floats2half2_rn(v3.z, v3.w); H1.w = *(u32*)&h;
            u32 off0 = (u32)fr * 128 + (u32)ffo * 2;
            u32 off1 = off0 + 16;
            *(uint4*)(smem + fbo + (off0 ^ ((off0 >> 3) & 0x70))) = H0;
            *(uint4*)(smem + fbo + (off1 ^ ((off1 >> 3) & 0x70))) = H1;
        }

        // single barrier: all warps done with MMA(c-1) and convert(c)
        __syncthreads();

        // ---- prefetch next W chunk (safe: everyone is past MMA(c-1)) ----
        if (c + 1 < 8) {
            u32 nwb = sb + P_W + ((c + 1) & 1) * 16384;
            const unsigned char* gh = g_Whs + (c + 1) * 16384;
            #pragma unroll
            for (int a = 0; a < 4; ++a)
                cp16(nwb + watom + a * 4096, gh + watom + a * 4096);
            cp_commit();
            cp_wait1();   // W(c) resident before MMA(c)
        } else {
            cp_wait0();
        }

        // ---- issue feat LDGs for next chunk (hidden under MMA) ----
        if (c + 1 < 8) {
            const float* fp = fbase + (c + 1) * 64;
            v0 = *(const float4*)(fp + 0);
            v1 = *(const float4*)(fp + 4);
            v2 = *(const float4*)(fp + 8);
            v3 = *(const float4*)(fp + 12);
        }

        // ---- single-pass fp16 MMA: F·W ----
        const u32 fb = sb + fbo;
        #pragma unroll
        for (int ks = 0; ks < 4; ++ks) {
            const u32 akb = ((u32)(ks * 32) + ach) ^ lxor;
            const u32 bkb = ((u32)(ks * 32) + bk4) ^ lxor;
            u32 aF[2][4], bH[8];
            #pragma unroll
            for (int mt = 0; mt < 2; ++mt)
                ldsm_x4(aF[mt][0], aF[mt][1], aF[mt][2], aF[mt][3],
                        fb + abase + mt * 2048 + akb);
            ldsm_x4(bH[0], bH[1], bH[2], bH[3], wb + bbase4 + bkb);
            ldsm_x4(bH[4], bH[5], bH[6], bH[7], wb + bbase4 + 2048 + bkb);
            #pragma unroll
            for (int mt = 0; mt < 2; ++mt)
                #pragma unroll
                for (int nt = 0; nt < 4; ++nt)
                    mma16816h(acc[mt][nt], aF[mt], bH + nt * 2);
        }
    }

    float csum = (cs0 + cs1) + (cs2 + cs3);
    csum += __shfl_xor_sync(0xffffffffu, csum, 1);
    csum += __shfl_xor_sync(0xffffffffu, csum, 2);
    if ((t & 3) == 0) chRow[fr] = 1.f / (1.f + expf(-(csum + bch[0])));
    __syncthreads();

    const float nls = -0.125f * loc_p[0];
    const int g = lid >> 2, tg = lid & 3;
    #pragma unroll
    for (int mt = 0; mt < 2; ++mt) {
        #pragma unroll
        for (int half = 0; half < 2; ++half) {
            int il = wm * 32 + mt * 16 + g + half * 8;
            size_t row = (size_t)(rowBase + il);
            float cr = chRow[il];
            #pragma unroll
            for (int nt = 0; nt < 4; ++nt) {
                int jl = wn * 32 + nt * 8 + tg * 2;
                float sc = (jl < 64) ? (nls * cr) : cr;
                float c0 = acc[mt][nt][half * 2 + 0] * sc;
                float c1 = acc[mt][nt][half * 2 + 1] * sc;
                __half2 h2 = __floats2half2_rn(c0, c1);
                if (jl < 64) {
                    *(__half2*)&g_Qh[row * D_DIM + jl] = h2;
                } else {
                    *(__half2*)&g_Kh[row * D_DIM + jl - 64] = h2;
                }
            }
        }
    }
}

// =================================================================
// energy: persistent, 4 CTAs/SM (128 threads), job tile 64(i) x 64(j)
// single-pass fp16 MMA; A hoisted; K double-buffered cp.async;
// epilogue: rcp TABLE + shuffle-packed STG.128. (unchanged from R15)
// smem: Q 0(8K), Kbuf0 8K, Kbuf1 16K -> 24KB
// =================================================================
#define E_Q 0
#define E_K 8192
#define E_SMEM 24576

__global__ __launch_bounds__(128, 4) void energy_kernel(float* __restrict__ out)
{
    extern __shared__ char smem[];
    const u32 sb = smem_u32(smem);

    const int t = threadIdx.x;
    const int wid = t >> 5, lid = t & 31;
    const int wm = wid & 1, wn = wid >> 1;

    const int js = (int)(((long long)blockIdx.x * TOTAL_JOBS) / EGRID);
    const int je = (int)(((long long)(blockIdx.x + 1) * TOTAL_JOBS) / EGRID);

    const int lc16 = t & 7;
    const int row16 = t >> 3;     // + 16*l

    const u32 lxor  = ((u32)(lid & 7)) << 4;
    const u32 abase = (u32)((wm * 32) + (lid & 7) + ((lid >> 3) & 1) * 8) * 128;
    const u32 ach   = ((u32)(lid >> 4) & 1) * 16;
    const u32 bbase4 = (u32)((wn * 32) + ((lid >> 4) & 1) * 8 + (lid & 7)) * 128;
    const u32 bk4    = ((u32)(lid >> 3) & 1) * 16;

    // prefetch K for first job
    {
        int job = js;
        int ib = job >> 6;
        size_t krow0 = (size_t)(ib >> 6) * S_DIM + (size_t)(job & 63) * 64;
        u32 kb = sb + E_K;
        #pragma unroll
        for (int l = 0; l < 4; ++l) {
            int row = row16 + 16 * l;
            u32 off = (u32)row * 128 + (u32)lc16 * 16;
            u32 swo = off ^ ((off >> 3) & 0x70);
            cp16(kb + swo, (const char*)(g_Kh + (krow0 + row) * D_DIM) + lc16 * 16);
        }
        cp_commit();
    }

    int curIb = -1;
    u32 afH[4][2][4];   // hoisted A fragments: [ks][mt][4]

    for (int job = js; job < je; ++job) {
        const int ib = job >> 6;
        const int jt = job & 63;
        const int buf = (job - js) & 1;
        const u32 kb = sb + E_K + buf * 8192;

        cp_wait0();
        __syncthreads();

        if (ib != curIb) {
            size_t qrow0 = (size_t)ib * 64;
            #pragma unroll
            for (int l = 0; l < 4; ++l) {
                int row = row16 + 16 * l;
                u32 off = (u32)row * 128 + (u32)lc16 * 16;
                u32 swo = off ^ ((off >> 3) & 0x70);
                *(uint4*)(smem + E_Q + swo) =
                    *(const uint4*)((const char*)(g_Qh + (qrow0 + row) * D_DIM) + lc16 * 16);
            }
            curIb = ib;
            __syncthreads();
            #pragma unroll
            for (int ks = 0; ks < 4; ++ks) {
                const u32 akb = ((u32)(ks * 32) + ach) ^ lxor;
                #pragma unroll
                for (int mt = 0; mt < 2; ++mt)
                    ldsm_x4(afH[ks][mt][0], afH[ks][mt][1], afH[ks][mt][2], afH[ks][mt][3],
                            sb + E_Q + abase + mt * 2048 + akb);
            }
        }

        // prefetch next K (overlaps MMA)
        if (job + 1 < je) {
            int nj = job + 1;
            int nib = nj >> 6;
            size_t krow0 = (size_t)(nib >> 6) * S_DIM + (size_t)(nj & 63) * 64;
            u32 nkb = sb + E_K + (buf ^ 1) * 8192;
            #pragma unroll
            for (int l = 0; l < 4; ++l) {
                int row = row16 + 16 * l;
                u32 off = (u32)row * 128 + (u32)lc16 * 16;
                u32 swo = off ^ ((off >> 3) & 0x70);
                cp16(nkb + swo, (const char*)(g_Kh + (krow0 + row) * D_DIM) + lc16 * 16);
            }
            cp_commit();
        }

        // ---- single-pass fp16 MMA, A hoisted ----
        float acc[2][4][4] = {};
        #pragma unroll
        for (int ks = 0; ks < 4; ++ks) {
            const u32 bkb = ((u32)(ks * 32) + bk4) ^ lxor;
            u32 bH[8];
            ldsm_x4(bH[0], bH[1], bH[2], bH[3], kb + bbase4 + bkb);
            ldsm_x4(bH[4], bH[5], bH[6], bH[7], kb + bbase4 + 2048 + bkb);
            #pragma unroll
            for (int mt = 0; mt < 2; ++mt)
                #pragma unroll
                for (int nt = 0; nt < 4; ++nt)
                    mma16816h(acc[mt][nt], afH[ks][mt], bH + nt * 2);
        }

        // ---- epilogue: v * table-rcp(|i-j|), shuffle-packed STG.128 ----
        const int iPos0 = (ib & 63) * 64;
        const int jj0 = jt * 64;
        const int g = lid >> 2, tg = lid & 3;
        const int colbase = ((tg & 1) << 3) + ((tg & 2) << 1);  // 0,8,4,12
        float* ob = out + ((size_t)ib * 64) * S_DIM + jj0;
        #pragma unroll
        for (int mt = 0; mt < 2; ++mt) {
            #pragma unroll
            for (int half = 0; half < 2; ++half) {
                int il = wm * 32 + mt * 16 + g + half * 8;
                int ip = iPos0 + il;
                int kbase = 4096 + ip - jj0;
                float* orow = ob + (size_t)il * S_DIM;
                #pragma unroll
                for (int grp = 0; grp < 2; ++grp) {
                    int jl0 = wn * 32 + grp * 16 + tg * 2;
                    float2 rX = g_rcp[kbase - jl0];
                    float2 rY = g_rcp[kbase - jl0 - 8];
                    const int nt0 = grp * 2, nt1 = grp * 2 + 1;
                    float Xx = acc[mt][nt0][half*2+0] * rX.x;
                    float Xy = acc[mt][nt0][half*2+1] * rX.y;
                    float Yx = acc[mt][nt1][half*2+0] * rY.x;
                    float Yy = acc[mt][nt1][half*2+1] * rY.y;
                    float pXx = __shfl_xor_sync(0xffffffffu, Xx, 1);
                    float pXy = __shfl_xor_sync(0xffffffffu, Xy, 1);
                    float pYx = __shfl_xor_sync(0xffffffffu, Yx, 1);
                    float pYy = __shfl_xor_sync(0xffffffffu, Yy, 1);
                    float4 F = (tg & 1) ? make_float4(pYx, pYy, Yx, Yy)
                                        : make_float4(Xx, Xy, pXx, pXy);
                    int col = wn * 32 + grp * 16 + colbase;
                    *(float4*)(orow + col) = F;
                }
            }
        }
    }
}

extern "C" void kernel_launch(void* const* d_in, const int* in_sizes, int n_in,
                              void* d_out, int out_size) {
    const float* feat = (const float*)d_in[0];
    const float* Wq   = (const float*)d_in[1];
    const float* Wk   = (const float*)d_in[2];
    const float* wch  = (const float*)d_in[3];
    const float* bch  = (const float*)d_in[4];
    const float* ls   = (const float*)d_in[5];
    float* out = (float*)d_out;

    cudaFuncSetAttribute(proj_kernel, cudaFuncAttributeMaxDynamicSharedMemorySize, P_SMEM);
    cudaFuncSetAttribute(energy_kernel, cudaFuncAttributeMaxDynamicSharedMemorySize, E_SMEM);

    wsetup_kernel<<<32, 256>>>(Wq, Wk);
    proj_kernel<<<(B_DIM * S_DIM) / 64, 256, P_SMEM>>>(feat, wch, bch, ls);
    energy_kernel<<<EGRID, 128, E_SMEM>>>(out);
}